// round 16
// baseline (speedup 1.0000x reference)
#include <cuda_runtime.h>
#include <math.h>

#define BATCH 8
#define VDIM 5000
#define CDIM 256
#define KDIM 200
#define NB   20
#define NPAN (KDIM/NB)
#define NSYS (BATCH*KDIM)   // 1600
#define MROW 204            // padded row stride of M
#define PROW 184            // padded row stride of P^T

// Scratch (device globals)
__device__ float g_Ap[3][BATCH*KDIM*CDIM];
__device__ float g_Bp[3][BATCH*KDIM*CDIM];
__device__ float g_S [BATCH*KDIM*KDIM];
__device__ float g_R [BATCH*KDIM*KDIM];
__device__ float g_M   [(size_t)NSYS*KDIM*MROW];
__device__ float g_P   [(size_t)NSYS*NB*PROW];
__device__ float g_RHS [NSYS*KDIM];
__device__ float g_DINV[NSYS*KDIM];
__device__ float g_DSH [NSYS*KDIM];

__device__ __constant__ int c_vstart[3] = {0, 1672, 3344};
__device__ __constant__ int c_vlen[3]   = {1672, 1672, 1656};

// ---------------------------------------------------------------------------
// Kernel 1: partial A[b,k,c] over a V chunk. grid (4,4,48)
// ---------------------------------------------------------------------------
__global__ __launch_bounds__(256) void k_gemm_feat(
    const float* __restrict__ fx, const float* __restrict__ fy,
    const float* __restrict__ ex, const float* __restrict__ ey)
{
    const int bz    = blockIdx.z;
    const int b     = bz & 7;
    const int which = (bz >> 3) & 1;
    const int vs    = bz >> 4;
    const float* E = (which ? ey : ex) + (size_t)b*KDIM*VDIM;
    const float* F = (which ? fy : fx) + (size_t)b*VDIM*CDIM;
    float*       C = (which ? g_Bp[vs] : g_Ap[vs]) + (size_t)b*KDIM*CDIM;

    const int vbeg = c_vstart[vs];
    const int vend = vbeg + c_vlen[vs];

    const int m0 = blockIdx.y * 64;
    const int n0 = blockIdx.x * 64;

    __shared__ float As[2][8][64];
    __shared__ float Bs[2][8][64];

    const int tid = threadIdx.x;
    const int tx  = tid & 15;
    const int ty  = tid >> 4;

    const bool isA = tid < 128;
    const int  t2  = tid & 127;
    const int  lrow = t2 >> 1;
    const int  lv4  = (t2 & 1) * 4;
    const int  fvr  = t2 >> 4;
    const int  fc4  = (t2 & 15) * 4;
    const bool arow_ok = (m0 + lrow < KDIM);

    float acc[4][4];
    #pragma unroll
    for (int i = 0; i < 4; ++i)
        #pragma unroll
        for (int j = 0; j < 4; ++j) acc[i][j] = 0.f;

    {
        float4 pre = make_float4(0.f,0.f,0.f,0.f);
        if (isA) {
            if (arow_ok)
                pre = *reinterpret_cast<const float4*>(E + (size_t)(m0 + lrow)*VDIM + vbeg + lv4);
            As[0][lv4+0][lrow] = pre.x; As[0][lv4+1][lrow] = pre.y;
            As[0][lv4+2][lrow] = pre.z; As[0][lv4+3][lrow] = pre.w;
        } else {
            pre = *reinterpret_cast<const float4*>(F + (size_t)(vbeg + fvr)*CDIM + n0 + fc4);
            *reinterpret_cast<float4*>(&Bs[0][fvr][fc4]) = pre;
        }
    }
    __syncthreads();

    int buf = 0;
    for (int v0 = vbeg; v0 < vend; v0 += 8) {
        const int vn = v0 + 8;
        const bool has = vn < vend;
        float4 nxt = make_float4(0.f,0.f,0.f,0.f);
        if (has) {
            if (isA) {
                if (arow_ok)
                    nxt = *reinterpret_cast<const float4*>(E + (size_t)(m0 + lrow)*VDIM + vn + lv4);
            } else {
                nxt = *reinterpret_cast<const float4*>(F + (size_t)(vn + fvr)*CDIM + n0 + fc4);
            }
        }

        #pragma unroll
        for (int kk = 0; kk < 8; ++kk) {
            float4 a  = *reinterpret_cast<const float4*>(&As[buf][kk][ty*4]);
            float4 bb = *reinterpret_cast<const float4*>(&Bs[buf][kk][tx*4]);
            float am[4] = {a.x,a.y,a.z,a.w};
            float bn[4] = {bb.x,bb.y,bb.z,bb.w};
            #pragma unroll
            for (int i2 = 0; i2 < 4; ++i2)
                #pragma unroll
                for (int j2 = 0; j2 < 4; ++j2)
                    acc[i2][j2] = fmaf(am[i2], bn[j2], acc[i2][j2]);
        }

        if (has) {
            const int nb = buf ^ 1;
            if (isA) {
                As[nb][lv4+0][lrow] = nxt.x; As[nb][lv4+1][lrow] = nxt.y;
                As[nb][lv4+2][lrow] = nxt.z; As[nb][lv4+3][lrow] = nxt.w;
            } else {
                *reinterpret_cast<float4*>(&Bs[nb][fvr][fc4]) = nxt;
            }
        }
        __syncthreads();
        buf ^= 1;
    }

    #pragma unroll
    for (int i2 = 0; i2 < 4; ++i2) {
        int k = m0 + ty*4 + i2;
        if (k < KDIM) {
            float4 v = make_float4(acc[i2][0], acc[i2][1], acc[i2][2], acc[i2][3]);
            *reinterpret_cast<float4*>(C + (size_t)k*CDIM + n0 + tx*4) = v;
        }
    }
}

// ---------------------------------------------------------------------------
// Kernel 2: S[b] = A A^T, R[b] = Bc A^T, summing the 3 V-chunk partials at
// load time (folds the old k_reduce into the gram GEMM).
// ---------------------------------------------------------------------------
__global__ __launch_bounds__(256) void k_gemm_gram()
{
    const int bz    = blockIdx.z;
    const int b     = bz & 7;
    const int which = bz >> 3;
    const size_t ob = (size_t)b*KDIM*CDIM;
    const float* X0 = (which ? g_Bp[0] : g_Ap[0]) + ob;
    const float* X1 = (which ? g_Bp[1] : g_Ap[1]) + ob;
    const float* X2 = (which ? g_Bp[2] : g_Ap[2]) + ob;
    const float* Y0 = g_Ap[0] + ob;
    const float* Y1 = g_Ap[1] + ob;
    const float* Y2 = g_Ap[2] + ob;
    float*       C  = (which ? g_R : g_S) + (size_t)b*KDIM*KDIM;

    const int m0 = blockIdx.y * 64;
    const int n0 = blockIdx.x * 64;

    __shared__ float As[16][64];
    __shared__ float Bs[16][64];

    const int tid = threadIdx.x;
    const int tx  = tid & 15;
    const int ty  = tid >> 4;
    const int lr  = tid >> 2;
    const int lc4 = (tid & 3) * 4;

    float acc[4][4];
    #pragma unroll
    for (int i = 0; i < 4; ++i)
        #pragma unroll
        for (int j = 0; j < 4; ++j) acc[i][j] = 0.f;

    for (int c0 = 0; c0 < CDIM; c0 += 16) {
        float4 xa = make_float4(0.f,0.f,0.f,0.f), yb = make_float4(0.f,0.f,0.f,0.f);
        if (m0 + lr < KDIM) {
            const size_t off = (size_t)(m0+lr)*CDIM + c0 + lc4;
            float4 a0 = *reinterpret_cast<const float4*>(X0 + off);
            float4 a1 = *reinterpret_cast<const float4*>(X1 + off);
            float4 a2 = *reinterpret_cast<const float4*>(X2 + off);
            xa = make_float4(a0.x+a1.x+a2.x, a0.y+a1.y+a2.y, a0.z+a1.z+a2.z, a0.w+a1.w+a2.w);
        }
        if (n0 + lr < KDIM) {
            const size_t off = (size_t)(n0+lr)*CDIM + c0 + lc4;
            float4 b0 = *reinterpret_cast<const float4*>(Y0 + off);
            float4 b1 = *reinterpret_cast<const float4*>(Y1 + off);
            float4 b2 = *reinterpret_cast<const float4*>(Y2 + off);
            yb = make_float4(b0.x+b1.x+b2.x, b0.y+b1.y+b2.y, b0.z+b1.z+b2.z, b0.w+b1.w+b2.w);
        }
        __syncthreads();
        As[lc4+0][lr] = xa.x; As[lc4+1][lr] = xa.y; As[lc4+2][lr] = xa.z; As[lc4+3][lr] = xa.w;
        Bs[lc4+0][lr] = yb.x; Bs[lc4+1][lr] = yb.y; Bs[lc4+2][lr] = yb.z; Bs[lc4+3][lr] = yb.w;
        __syncthreads();
        #pragma unroll
        for (int kk = 0; kk < 16; ++kk) {
            float4 a  = *reinterpret_cast<const float4*>(&As[kk][ty*4]);
            float4 bb = *reinterpret_cast<const float4*>(&Bs[kk][tx*4]);
            float am[4] = {a.x,a.y,a.z,a.w}, bn[4] = {bb.x,bb.y,bb.z,bb.w};
            #pragma unroll
            for (int i2 = 0; i2 < 4; ++i2)
                #pragma unroll
                for (int j2 = 0; j2 < 4; ++j2)
                    acc[i2][j2] = fmaf(am[i2], bn[j2], acc[i2][j2]);
        }
    }

    for (int i2 = 0; i2 < 4; ++i2) {
        int k = m0 + ty*4 + i2;
        if (k >= KDIM) continue;
        for (int j2 = 0; j2 < 4; ++j2) {
            int l = n0 + tx*4 + j2;
            if (l >= KDIM) continue;
            C[(size_t)k*KDIM + l] = acc[i2][j2];
        }
    }
}

// ---------------------------------------------------------------------------
// k_prep: scaling, gamma/lambda, diag shifts, rhs copy. grid (KDIM, BATCH)
// ---------------------------------------------------------------------------
__global__ __launch_bounds__(256) void k_prep(
    const float* __restrict__ evx_all, const float* __restrict__ evy_all,
    const float* __restrict__ p_gamma, const float* __restrict__ p_lambda)
{
    __shared__ float red[8];
    const int irow = blockIdx.x;
    const int b    = blockIdx.y;
    const int sys  = b*KDIM + irow;
    const int tid  = threadIdx.x;
    const int lane = tid & 31;
    const int wid  = tid >> 5;

    const float* evx = evx_all + b*KDIM;
    const float* evy = evy_all + b*KDIM;

    const float graw  = p_gamma[0];
    const float lraw  = p_lambda[0];
    const float gamma = 1.f / (1.f + expf(-graw));
    const float sp    = fmaxf(lraw, 0.f) + log1pf(expf(-fabsf(lraw)));
    float lmbda = 10.f + sp * (1000.f - 10.f) / 1000.f;
    lmbda = fminf(fmaxf(lmbda, 10.f), 1000.f);

    float mv = 0.f;
    for (int j = tid; j < KDIM; j += 256) mv = fmaxf(mv, fmaxf(evx[j], evy[j]));
    #pragma unroll
    for (int o = 16; o > 0; o >>= 1) mv = fmaxf(mv, __shfl_xor_sync(0xffffffffu, mv, o));
    if (lane == 0) red[wid] = mv;
    __syncthreads();
    if (tid == 0) {
        float m2 = red[0];
        for (int w = 1; w < 8; ++w) m2 = fmaxf(m2, red[w]);
        red[0] = m2;
    }
    __syncthreads();
    const float scaling = red[0];

    const float gx = powf(evx[irow] / scaling, gamma);
    const float dx = 1.f / (gx*gx + 1.f);

    for (int k = tid; k < KDIM; k += 256) {
        float gy  = powf(evy[k] / scaling, gamma);
        float dy  = 1.f / (gy*gy + 1.f);
        float mre = gy*dy - gx*dx;
        float mim = dy - dx;
        g_DSH[sys*KDIM + k] = lmbda * (mre*mre + mim*mim);
        g_RHS[sys*KDIM + k] = g_R[((size_t)b*KDIM + irow)*KDIM + k];
    }
}

// ---------------------------------------------------------------------------
// k_panel<P>: diag factor + forward-solve step + panel TRSM. grid (NSYS), 192 thr.
// TRSM rows loaded/stored as float4 (rows are 16B-aligned: MROW, KDIM, K0
// all multiples of 4) to cut L1tex wavefronts 4x.
// ---------------------------------------------------------------------------
template<int P>
__global__ __launch_bounds__(192) void k_panel()
{
    constexpr int K0   = P*NB;
    constexpr int KEND = K0 + NB;
    constexpr int T    = KDIM - KEND;
    const unsigned FMASK = 0x000FFFFFu;

    __shared__ float Dblk[NB][NB+1];
    __shared__ float dinv_s[NB];

    const int sys = blockIdx.x;
    const int b   = sys / KDIM;
    const int tid = threadIdx.x;
    const int lane = tid & 31;
    const int wid  = tid >> 5;

    const float* Sb = g_S + (size_t)b*KDIM*KDIM;
    float* M = g_M + (size_t)sys*KDIM*MROW;

    // load diag block (lower part)
    for (int idx = tid; idx < NB*NB; idx += 192) {
        int r = idx / NB, c = idx - r*NB;
        if (c <= r) {
            float v;
            if (P == 0) {
                v = Sb[(K0 + r)*KDIM + K0 + c];
                if (c == r) v += g_DSH[sys*KDIM + K0 + r];
            } else {
                v = M[(size_t)(K0 + r)*MROW + K0 + c];
            }
            Dblk[r][c] = v;
        }
    }
    __syncthreads();

    if (wid == 0 && lane < NB) {
        float a[NB];
        #pragma unroll
        for (int m = 0; m < NB; ++m) a[m] = (m <= lane) ? Dblk[lane][m] : 0.f;
        float myinv = 0.f;
        #pragma unroll
        for (int kk = 0; kk < NB; ++kk) {
            float dval = __shfl_sync(FMASK, a[kk], kk);
            float inv  = rsqrtf(dval);
            if (lane == kk) { a[kk] = dval * inv; myinv = inv; }
            if (lane >  kk) a[kk] *= inv;
            #pragma unroll
            for (int m = kk + 1; m < NB; ++m) {
                float Lmk = __shfl_sync(FMASK, a[kk], m);
                if (lane >= m) a[m] = fmaf(-a[kk], Lmk, a[m]);
            }
        }
        #pragma unroll
        for (int m = 0; m < NB; ++m) {
            if (m <= lane) {
                Dblk[lane][m] = a[m];
                M[(size_t)(K0 + lane)*MROW + K0 + m] = a[m];
            }
        }
        dinv_s[lane] = myinv;
        g_DINV[sys*KDIM + K0 + lane] = myinv;

        // forward-solve this block's y
        float r = g_RHS[sys*KDIM + K0 + lane];
        #pragma unroll
        for (int m = 0; m < NB; ++m) {
            float ym = __shfl_sync(FMASK, r, m) * __shfl_sync(FMASK, myinv, m);
            if (lane == m) r = ym;
            if (lane >  m) r = fmaf(-a[m], ym, r);
        }
        g_RHS[sys*KDIM + K0 + lane] = r;
    }
    __syncthreads();

    // panel TRSM: one row per thread, float4 loads/stores
    if (T > 0 && tid < T) {
        const int i = KEND + tid;
        float row[NB];
        if (P == 0) {
            const float4* src = reinterpret_cast<const float4*>(Sb + (size_t)i*KDIM + K0);
            #pragma unroll
            for (int m4 = 0; m4 < NB/4; ++m4) {
                float4 v = src[m4];
                row[4*m4+0]=v.x; row[4*m4+1]=v.y; row[4*m4+2]=v.z; row[4*m4+3]=v.w;
            }
        } else {
            const float4* src = reinterpret_cast<const float4*>(M + (size_t)i*MROW + K0);
            #pragma unroll
            for (int m4 = 0; m4 < NB/4; ++m4) {
                float4 v = src[m4];
                row[4*m4+0]=v.x; row[4*m4+1]=v.y; row[4*m4+2]=v.z; row[4*m4+3]=v.w;
            }
        }
        #pragma unroll
        for (int j = 0; j < NB; ++j) {
            float s = row[j];
            #pragma unroll
            for (int m = 0; m < j; ++m) s = fmaf(-row[m], Dblk[j][m], s);
            row[j] = s * dinv_s[j];
        }
        {
            float4* dst = reinterpret_cast<float4*>(M + (size_t)i*MROW + K0);
            #pragma unroll
            for (int m4 = 0; m4 < NB/4; ++m4)
                dst[m4] = make_float4(row[4*m4+0], row[4*m4+1], row[4*m4+2], row[4*m4+3]);
        }
        #pragma unroll
        for (int m = 0; m < NB; ++m)
            g_P[(size_t)sys*NB*PROW + m*PROW + tid] = row[m];
    }
}

// ---------------------------------------------------------------------------
// k_trail<P>: batched trailing update (64x64 tiles) + rhs rank-NB update.
// grid (NTILES+1, NSYS), 256 threads.
// ---------------------------------------------------------------------------
template<int P>
__global__ __launch_bounds__(256) void k_trail()
{
    constexpr int K0   = P*NB;
    constexpr int KEND = K0 + NB;
    constexpr int T    = KDIM - KEND;
    constexpr int NT64 = (T + 63) / 64;
    constexpr int NTILES = NT64*(NT64+1)/2;

    const int sys = blockIdx.y;
    const int tid = threadIdx.x;
    const float* Pp = g_P + (size_t)sys*NB*PROW;

    if ((int)blockIdx.x == NTILES) {
        // rhs update: rhs[KEND+r] -= sum_m P[m][r] * y[m]
        __shared__ float ys[NB];
        if (tid < NB) ys[tid] = g_RHS[sys*KDIM + K0 + tid];
        __syncthreads();
        for (int r = tid; r < T; r += 256) {
            float s = g_RHS[sys*KDIM + KEND + r];
            #pragma unroll
            for (int m = 0; m < NB; ++m) s = fmaf(-Pp[m*PROW + r], ys[m], s);
            g_RHS[sys*KDIM + KEND + r] = s;
        }
        return;
    }

    // tile -> (ri, cj)
    int rem = blockIdx.x, ri = 0;
    while (rem > ri) { rem -= ri + 1; ++ri; }
    const int cj = rem;

    __shared__ float As[NB][68];
    __shared__ float Bs[NB][68];
    for (int idx = tid; idx < NB*64; idx += 256) {
        int k = idx >> 6, rr = idx & 63;
        int ra = 64*ri + rr;
        int rb = 64*cj + rr;
        As[k][rr] = (ra < T) ? Pp[k*PROW + ra] : 0.f;
        Bs[k][rr] = (rb < T) ? Pp[k*PROW + rb] : 0.f;
    }
    __syncthreads();

    const int tx = tid & 15;
    const int ty = tid >> 4;

    float acc[4][4];
    #pragma unroll
    for (int i2 = 0; i2 < 4; ++i2)
        #pragma unroll
        for (int j2 = 0; j2 < 4; ++j2) acc[i2][j2] = 0.f;

    #pragma unroll
    for (int k = 0; k < NB; ++k) {
        float4 av = *reinterpret_cast<const float4*>(&As[k][4*ty]);
        float4 bv = *reinterpret_cast<const float4*>(&Bs[k][4*tx]);
        float am[4] = {av.x,av.y,av.z,av.w};
        float bn[4] = {bv.x,bv.y,bv.z,bv.w};
        #pragma unroll
        for (int i2 = 0; i2 < 4; ++i2)
            #pragma unroll
            for (int j2 = 0; j2 < 4; ++j2)
                acc[i2][j2] = fmaf(am[i2], bn[j2], acc[i2][j2]);
    }

    float* M = g_M + (size_t)sys*KDIM*MROW;
    const int b = sys / KDIM;
    const float* Sb = g_S + (size_t)b*KDIM*KDIM;

    #pragma unroll
    for (int i2 = 0; i2 < 4; ++i2) {
        const int rr = 64*ri + 4*ty + i2;
        if (rr >= T) continue;
        const int i = KEND + rr;
        const int ccb = 64*cj + 4*tx;
        if (ccb + 3 < rr) {
            // pure off-diagonal float4 path
            float4 v;
            if (P == 0) v = *reinterpret_cast<const float4*>(&Sb[(size_t)i*KDIM + KEND + ccb]);
            else        v = *reinterpret_cast<const float4*>(&M[(size_t)i*MROW + KEND + ccb]);
            v.x -= acc[i2][0]; v.y -= acc[i2][1];
            v.z -= acc[i2][2]; v.w -= acc[i2][3];
            *reinterpret_cast<float4*>(&M[(size_t)i*MROW + KEND + ccb]) = v;
        } else if (ccb <= rr) {
            #pragma unroll
            for (int q = 0; q < 4; ++q) {
                const int c = ccb + q;
                if (c > rr) break;
                float v;
                if (P == 0) {
                    v = Sb[(size_t)i*KDIM + KEND + c];
                    if (c == rr) v += g_DSH[sys*KDIM + i];
                } else {
                    v = M[(size_t)i*MROW + KEND + c];
                }
                M[(size_t)i*MROW + KEND + c] = v - acc[i2][q];
            }
        }
    }
}

// ---------------------------------------------------------------------------
// k_back<BLK>: one backward-substitution block step; writes final x to out.
// grid (NSYS), 192 thr.
// ---------------------------------------------------------------------------
template<int BLK>
__global__ __launch_bounds__(192) void k_back(float* __restrict__ out)
{
    constexpr int BK0 = BLK*NB;
    const unsigned FMASK = 0x000FFFFFu;
    __shared__ float xs[NB];

    const int sys = blockIdx.x;
    const int tid = threadIdx.x;
    const int lane = tid & 31;
    const int wid  = tid >> 5;
    const float* M = g_M + (size_t)sys*KDIM*MROW;

    if (wid == 0 && lane < NB) {
        float a[NB];
        #pragma unroll
        for (int m = 0; m < NB; ++m)
            a[m] = (m >= lane) ? M[(size_t)(BK0 + m)*MROW + BK0 + lane] : 0.f;
        float dv = g_DINV[sys*KDIM + BK0 + lane];
        float r  = g_RHS[sys*KDIM + BK0 + lane];
        #pragma unroll
        for (int m = NB - 1; m >= 0; --m) {
            float xm = __shfl_sync(FMASK, r, m) * __shfl_sync(FMASK, dv, m);
            if (lane == m) r = xm;
            if (lane <  m) r = fmaf(-a[m], xm, r);
        }
        xs[lane] = r;
        out[(size_t)sys*KDIM + BK0 + lane] = r;
    }
    __syncthreads();

    for (int i = tid; i < BK0; i += 192) {
        float s = g_RHS[sys*KDIM + i];
        #pragma unroll
        for (int m = 0; m < NB; ++m)
            s = fmaf(-M[(size_t)(BK0 + m)*MROW + i], xs[m], s);
        g_RHS[sys*KDIM + i] = s;
    }
}

// ---------------------------------------------------------------------------
extern "C" void kernel_launch(void* const* d_in, const int* in_sizes, int n_in,
                              void* d_out, int out_size)
{
    const float* feat_x  = (const float*)d_in[0];
    const float* feat_y  = (const float*)d_in[1];
    const float* evals_x = (const float*)d_in[2];
    const float* evals_y = (const float*)d_in[3];
    const float* evtx    = (const float*)d_in[4];
    const float* evty    = (const float*)d_in[5];
    const float* graw    = (const float*)d_in[6];
    const float* lraw    = (const float*)d_in[7];
    float* out = (float*)d_out;

    k_gemm_feat<<<dim3(4, 4, 48), 256>>>(feat_x, feat_y, evtx, evty);
    k_gemm_gram<<<dim3(4, 4, 16), 256>>>();
    k_prep<<<dim3(KDIM, BATCH), 256>>>(evals_x, evals_y, graw, lraw);

    k_panel<0><<<NSYS, 192>>>();  k_trail<0><<<dim3(7, NSYS), 256>>>();
    k_panel<1><<<NSYS, 192>>>();  k_trail<1><<<dim3(7, NSYS), 256>>>();
    k_panel<2><<<NSYS, 192>>>();  k_trail<2><<<dim3(7, NSYS), 256>>>();
    k_panel<3><<<NSYS, 192>>>();  k_trail<3><<<dim3(4, NSYS), 256>>>();
    k_panel<4><<<NSYS, 192>>>();  k_trail<4><<<dim3(4, NSYS), 256>>>();
    k_panel<5><<<NSYS, 192>>>();  k_trail<5><<<dim3(4, NSYS), 256>>>();
    k_panel<6><<<NSYS, 192>>>();  k_trail<6><<<dim3(2, NSYS), 256>>>();
    k_panel<7><<<NSYS, 192>>>();  k_trail<7><<<dim3(2, NSYS), 256>>>();
    k_panel<8><<<NSYS, 192>>>();  k_trail<8><<<dim3(2, NSYS), 256>>>();
    k_panel<9><<<NSYS, 192>>>();

    k_back<9><<<NSYS, 192>>>(out);
    k_back<8><<<NSYS, 192>>>(out);
    k_back<7><<<NSYS, 192>>>(out);
    k_back<6><<<NSYS, 192>>>(out);
    k_back<5><<<NSYS, 192>>>(out);
    k_back<4><<<NSYS, 192>>>(out);
    k_back<3><<<NSYS, 192>>>(out);
    k_back<2><<<NSYS, 192>>>(out);
    k_back<1><<<NSYS, 192>>>(out);
    k_back<0><<<NSYS, 192>>>(out);
}

// round 17
// speedup vs baseline: 1.4481x; 1.4481x over previous
#include <cuda_runtime.h>
#include <math.h>

#define BATCH 8
#define VDIM 5000
#define CDIM 256
#define KDIM 200
#define NB   20
#define NPAN (KDIM/NB)
#define NSYS (BATCH*KDIM)   // 1600
#define MROW 204            // padded row stride of M
#define PROW 184            // padded row stride of P^T

// Scratch (device globals)
__device__ float g_Ap[3][BATCH*KDIM*CDIM];
__device__ float g_Bp[3][BATCH*KDIM*CDIM];
__device__ float g_S [BATCH*KDIM*KDIM];
__device__ float g_R [BATCH*KDIM*KDIM];
__device__ float g_M   [(size_t)NSYS*KDIM*MROW];
__device__ float g_P   [(size_t)NSYS*NB*PROW];
__device__ float g_RHS [NSYS*KDIM];
__device__ float g_DINV[NSYS*KDIM];
__device__ float g_DSH [NSYS*KDIM];

__device__ __constant__ int c_vstart[3] = {0, 1672, 3344};
__device__ __constant__ int c_vlen[3]   = {1672, 1672, 1656};

// ---------------------------------------------------------------------------
// Kernel 1: partial A[b,k,c] over a V chunk. grid (4,4,48)
// ---------------------------------------------------------------------------
__global__ __launch_bounds__(256) void k_gemm_feat(
    const float* __restrict__ fx, const float* __restrict__ fy,
    const float* __restrict__ ex, const float* __restrict__ ey)
{
    const int bz    = blockIdx.z;
    const int b     = bz & 7;
    const int which = (bz >> 3) & 1;
    const int vs    = bz >> 4;
    const float* E = (which ? ey : ex) + (size_t)b*KDIM*VDIM;
    const float* F = (which ? fy : fx) + (size_t)b*VDIM*CDIM;
    float*       C = (which ? g_Bp[vs] : g_Ap[vs]) + (size_t)b*KDIM*CDIM;

    const int vbeg = c_vstart[vs];
    const int vend = vbeg + c_vlen[vs];

    const int m0 = blockIdx.y * 64;
    const int n0 = blockIdx.x * 64;

    __shared__ float As[2][8][64];
    __shared__ float Bs[2][8][64];

    const int tid = threadIdx.x;
    const int tx  = tid & 15;
    const int ty  = tid >> 4;

    const bool isA = tid < 128;
    const int  t2  = tid & 127;
    const int  lrow = t2 >> 1;
    const int  lv4  = (t2 & 1) * 4;
    const int  fvr  = t2 >> 4;
    const int  fc4  = (t2 & 15) * 4;
    const bool arow_ok = (m0 + lrow < KDIM);

    float acc[4][4];
    #pragma unroll
    for (int i = 0; i < 4; ++i)
        #pragma unroll
        for (int j = 0; j < 4; ++j) acc[i][j] = 0.f;

    {
        float4 pre = make_float4(0.f,0.f,0.f,0.f);
        if (isA) {
            if (arow_ok)
                pre = *reinterpret_cast<const float4*>(E + (size_t)(m0 + lrow)*VDIM + vbeg + lv4);
            As[0][lv4+0][lrow] = pre.x; As[0][lv4+1][lrow] = pre.y;
            As[0][lv4+2][lrow] = pre.z; As[0][lv4+3][lrow] = pre.w;
        } else {
            pre = *reinterpret_cast<const float4*>(F + (size_t)(vbeg + fvr)*CDIM + n0 + fc4);
            *reinterpret_cast<float4*>(&Bs[0][fvr][fc4]) = pre;
        }
    }
    __syncthreads();

    int buf = 0;
    for (int v0 = vbeg; v0 < vend; v0 += 8) {
        const int vn = v0 + 8;
        const bool has = vn < vend;
        float4 nxt = make_float4(0.f,0.f,0.f,0.f);
        if (has) {
            if (isA) {
                if (arow_ok)
                    nxt = *reinterpret_cast<const float4*>(E + (size_t)(m0 + lrow)*VDIM + vn + lv4);
            } else {
                nxt = *reinterpret_cast<const float4*>(F + (size_t)(vn + fvr)*CDIM + n0 + fc4);
            }
        }

        #pragma unroll
        for (int kk = 0; kk < 8; ++kk) {
            float4 a  = *reinterpret_cast<const float4*>(&As[buf][kk][ty*4]);
            float4 bb = *reinterpret_cast<const float4*>(&Bs[buf][kk][tx*4]);
            float am[4] = {a.x,a.y,a.z,a.w};
            float bn[4] = {bb.x,bb.y,bb.z,bb.w};
            #pragma unroll
            for (int i2 = 0; i2 < 4; ++i2)
                #pragma unroll
                for (int j2 = 0; j2 < 4; ++j2)
                    acc[i2][j2] = fmaf(am[i2], bn[j2], acc[i2][j2]);
        }

        if (has) {
            const int nb = buf ^ 1;
            if (isA) {
                As[nb][lv4+0][lrow] = nxt.x; As[nb][lv4+1][lrow] = nxt.y;
                As[nb][lv4+2][lrow] = nxt.z; As[nb][lv4+3][lrow] = nxt.w;
            } else {
                *reinterpret_cast<float4*>(&Bs[nb][fvr][fc4]) = nxt;
            }
        }
        __syncthreads();
        buf ^= 1;
    }

    #pragma unroll
    for (int i2 = 0; i2 < 4; ++i2) {
        int k = m0 + ty*4 + i2;
        if (k < KDIM) {
            float4 v = make_float4(acc[i2][0], acc[i2][1], acc[i2][2], acc[i2][3]);
            *reinterpret_cast<float4*>(C + (size_t)k*CDIM + n0 + tx*4) = v;
        }
    }
}

// ---------------------------------------------------------------------------
// Kernel 2: S[b] = A A^T, R[b] = Bc A^T, summing the 3 V-chunk partials at
// load time.
// ---------------------------------------------------------------------------
__global__ __launch_bounds__(256) void k_gemm_gram()
{
    const int bz    = blockIdx.z;
    const int b     = bz & 7;
    const int which = bz >> 3;
    const size_t ob = (size_t)b*KDIM*CDIM;
    const float* X0 = (which ? g_Bp[0] : g_Ap[0]) + ob;
    const float* X1 = (which ? g_Bp[1] : g_Ap[1]) + ob;
    const float* X2 = (which ? g_Bp[2] : g_Ap[2]) + ob;
    const float* Y0 = g_Ap[0] + ob;
    const float* Y1 = g_Ap[1] + ob;
    const float* Y2 = g_Ap[2] + ob;
    float*       C  = (which ? g_R : g_S) + (size_t)b*KDIM*KDIM;

    const int m0 = blockIdx.y * 64;
    const int n0 = blockIdx.x * 64;

    __shared__ float As[16][64];
    __shared__ float Bs[16][64];

    const int tid = threadIdx.x;
    const int tx  = tid & 15;
    const int ty  = tid >> 4;
    const int lr  = tid >> 2;
    const int lc4 = (tid & 3) * 4;

    float acc[4][4];
    #pragma unroll
    for (int i = 0; i < 4; ++i)
        #pragma unroll
        for (int j = 0; j < 4; ++j) acc[i][j] = 0.f;

    for (int c0 = 0; c0 < CDIM; c0 += 16) {
        float4 xa = make_float4(0.f,0.f,0.f,0.f), yb = make_float4(0.f,0.f,0.f,0.f);
        if (m0 + lr < KDIM) {
            const size_t off = (size_t)(m0+lr)*CDIM + c0 + lc4;
            float4 a0 = *reinterpret_cast<const float4*>(X0 + off);
            float4 a1 = *reinterpret_cast<const float4*>(X1 + off);
            float4 a2 = *reinterpret_cast<const float4*>(X2 + off);
            xa = make_float4(a0.x+a1.x+a2.x, a0.y+a1.y+a2.y, a0.z+a1.z+a2.z, a0.w+a1.w+a2.w);
        }
        if (n0 + lr < KDIM) {
            const size_t off = (size_t)(n0+lr)*CDIM + c0 + lc4;
            float4 b0 = *reinterpret_cast<const float4*>(Y0 + off);
            float4 b1 = *reinterpret_cast<const float4*>(Y1 + off);
            float4 b2 = *reinterpret_cast<const float4*>(Y2 + off);
            yb = make_float4(b0.x+b1.x+b2.x, b0.y+b1.y+b2.y, b0.z+b1.z+b2.z, b0.w+b1.w+b2.w);
        }
        __syncthreads();
        As[lc4+0][lr] = xa.x; As[lc4+1][lr] = xa.y; As[lc4+2][lr] = xa.z; As[lc4+3][lr] = xa.w;
        Bs[lc4+0][lr] = yb.x; Bs[lc4+1][lr] = yb.y; Bs[lc4+2][lr] = yb.z; Bs[lc4+3][lr] = yb.w;
        __syncthreads();
        #pragma unroll
        for (int kk = 0; kk < 16; ++kk) {
            float4 a  = *reinterpret_cast<const float4*>(&As[kk][ty*4]);
            float4 bb = *reinterpret_cast<const float4*>(&Bs[kk][tx*4]);
            float am[4] = {a.x,a.y,a.z,a.w}, bn[4] = {bb.x,bb.y,bb.z,bb.w};
            #pragma unroll
            for (int i2 = 0; i2 < 4; ++i2)
                #pragma unroll
                for (int j2 = 0; j2 < 4; ++j2)
                    acc[i2][j2] = fmaf(am[i2], bn[j2], acc[i2][j2]);
        }
    }

    for (int i2 = 0; i2 < 4; ++i2) {
        int k = m0 + ty*4 + i2;
        if (k >= KDIM) continue;
        for (int j2 = 0; j2 < 4; ++j2) {
            int l = n0 + tx*4 + j2;
            if (l >= KDIM) continue;
            C[(size_t)k*KDIM + l] = acc[i2][j2];
        }
    }
}

// ---------------------------------------------------------------------------
// k_prep: scaling, gamma/lambda, diag shifts, rhs copy. grid (KDIM, BATCH)
// ---------------------------------------------------------------------------
__global__ __launch_bounds__(256) void k_prep(
    const float* __restrict__ evx_all, const float* __restrict__ evy_all,
    const float* __restrict__ p_gamma, const float* __restrict__ p_lambda)
{
    __shared__ float red[8];
    const int irow = blockIdx.x;
    const int b    = blockIdx.y;
    const int sys  = b*KDIM + irow;
    const int tid  = threadIdx.x;
    const int lane = tid & 31;
    const int wid  = tid >> 5;

    const float* evx = evx_all + b*KDIM;
    const float* evy = evy_all + b*KDIM;

    const float graw  = p_gamma[0];
    const float lraw  = p_lambda[0];
    const float gamma = 1.f / (1.f + expf(-graw));
    const float sp    = fmaxf(lraw, 0.f) + log1pf(expf(-fabsf(lraw)));
    float lmbda = 10.f + sp * (1000.f - 10.f) / 1000.f;
    lmbda = fminf(fmaxf(lmbda, 10.f), 1000.f);

    float mv = 0.f;
    for (int j = tid; j < KDIM; j += 256) mv = fmaxf(mv, fmaxf(evx[j], evy[j]));
    #pragma unroll
    for (int o = 16; o > 0; o >>= 1) mv = fmaxf(mv, __shfl_xor_sync(0xffffffffu, mv, o));
    if (lane == 0) red[wid] = mv;
    __syncthreads();
    if (tid == 0) {
        float m2 = red[0];
        for (int w = 1; w < 8; ++w) m2 = fmaxf(m2, red[w]);
        red[0] = m2;
    }
    __syncthreads();
    const float scaling = red[0];

    const float gx = powf(evx[irow] / scaling, gamma);
    const float dx = 1.f / (gx*gx + 1.f);

    for (int k = tid; k < KDIM; k += 256) {
        float gy  = powf(evy[k] / scaling, gamma);
        float dy  = 1.f / (gy*gy + 1.f);
        float mre = gy*dy - gx*dx;
        float mim = dy - dx;
        g_DSH[sys*KDIM + k] = lmbda * (mre*mre + mim*mim);
        g_RHS[sys*KDIM + k] = g_R[((size_t)b*KDIM + irow)*KDIM + k];
    }
}

// ---------------------------------------------------------------------------
// k_panel<P>: diag factor + forward-solve step + panel TRSM. grid (NSYS), 192 thr.
// Diag block loaded as full 20x20 square via coalesced float4 (upper half is
// garbage but never read). TRSM rows as float4.
// ---------------------------------------------------------------------------
template<int P>
__global__ __launch_bounds__(192) void k_panel()
{
    constexpr int K0   = P*NB;
    constexpr int KEND = K0 + NB;
    constexpr int T    = KDIM - KEND;
    const unsigned FMASK = 0x000FFFFFu;

    __shared__ float Dblk[NB][NB+1];
    __shared__ float dinv_s[NB];

    const int sys = blockIdx.x;
    const int b   = sys / KDIM;
    const int tid = threadIdx.x;
    const int lane = tid & 31;
    const int wid  = tid >> 5;

    const float* Sb = g_S + (size_t)b*KDIM*KDIM;
    float* M = g_M + (size_t)sys*KDIM*MROW;

    // load full diag block square, coalesced float4 (100 vec loads)
    for (int idx = tid; idx < NB*(NB/4); idx += 192) {
        const int r  = idx / (NB/4);
        const int c4 = (idx - r*(NB/4)) * 4;
        float4 v;
        if (P == 0) v = *reinterpret_cast<const float4*>(Sb + (size_t)(K0 + r)*KDIM + K0 + c4);
        else        v = *reinterpret_cast<const float4*>(M  + (size_t)(K0 + r)*MROW + K0 + c4);
        Dblk[r][c4+0] = v.x; Dblk[r][c4+1] = v.y;
        Dblk[r][c4+2] = v.z; Dblk[r][c4+3] = v.w;
    }
    __syncthreads();
    if (P == 0 && tid < NB)
        Dblk[tid][tid] += g_DSH[sys*KDIM + K0 + tid];
    __syncthreads();

    if (wid == 0 && lane < NB) {
        float a[NB];
        #pragma unroll
        for (int m = 0; m < NB; ++m) a[m] = (m <= lane) ? Dblk[lane][m] : 0.f;
        float myinv = 0.f;
        #pragma unroll
        for (int kk = 0; kk < NB; ++kk) {
            float dval = __shfl_sync(FMASK, a[kk], kk);
            float inv  = rsqrtf(dval);
            if (lane == kk) { a[kk] = dval * inv; myinv = inv; }
            if (lane >  kk) a[kk] *= inv;
            #pragma unroll
            for (int m = kk + 1; m < NB; ++m) {
                float Lmk = __shfl_sync(FMASK, a[kk], m);
                if (lane >= m) a[m] = fmaf(-a[kk], Lmk, a[m]);
            }
        }
        #pragma unroll
        for (int m = 0; m < NB; ++m) {
            if (m <= lane) {
                Dblk[lane][m] = a[m];
                M[(size_t)(K0 + lane)*MROW + K0 + m] = a[m];
            }
        }
        dinv_s[lane] = myinv;
        g_DINV[sys*KDIM + K0 + lane] = myinv;

        // forward-solve this block's y
        float r = g_RHS[sys*KDIM + K0 + lane];
        #pragma unroll
        for (int m = 0; m < NB; ++m) {
            float ym = __shfl_sync(FMASK, r, m) * __shfl_sync(FMASK, myinv, m);
            if (lane == m) r = ym;
            if (lane >  m) r = fmaf(-a[m], ym, r);
        }
        g_RHS[sys*KDIM + K0 + lane] = r;
    }
    __syncthreads();

    // panel TRSM: one row per thread, float4 loads/stores
    if (T > 0 && tid < T) {
        const int i = KEND + tid;
        float row[NB];
        if (P == 0) {
            const float4* src = reinterpret_cast<const float4*>(Sb + (size_t)i*KDIM + K0);
            #pragma unroll
            for (int m4 = 0; m4 < NB/4; ++m4) {
                float4 v = src[m4];
                row[4*m4+0]=v.x; row[4*m4+1]=v.y; row[4*m4+2]=v.z; row[4*m4+3]=v.w;
            }
        } else {
            const float4* src = reinterpret_cast<const float4*>(M + (size_t)i*MROW + K0);
            #pragma unroll
            for (int m4 = 0; m4 < NB/4; ++m4) {
                float4 v = src[m4];
                row[4*m4+0]=v.x; row[4*m4+1]=v.y; row[4*m4+2]=v.z; row[4*m4+3]=v.w;
            }
        }
        #pragma unroll
        for (int j = 0; j < NB; ++j) {
            float s = row[j];
            #pragma unroll
            for (int m = 0; m < j; ++m) s = fmaf(-row[m], Dblk[j][m], s);
            row[j] = s * dinv_s[j];
        }
        {
            float4* dst = reinterpret_cast<float4*>(M + (size_t)i*MROW + K0);
            #pragma unroll
            for (int m4 = 0; m4 < NB/4; ++m4)
                dst[m4] = make_float4(row[4*m4+0], row[4*m4+1], row[4*m4+2], row[4*m4+3]);
        }
        #pragma unroll
        for (int m = 0; m < NB; ++m)
            g_P[(size_t)sys*NB*PROW + m*PROW + tid] = row[m];
    }
}

// ---------------------------------------------------------------------------
// k_trail<P>: batched trailing update (64x64 tiles) + rhs rank-NB update.
// grid (NTILES+1, NSYS), 256 threads.
// ---------------------------------------------------------------------------
template<int P>
__global__ __launch_bounds__(256) void k_trail()
{
    constexpr int K0   = P*NB;
    constexpr int KEND = K0 + NB;
    constexpr int T    = KDIM - KEND;
    constexpr int NT64 = (T + 63) / 64;
    constexpr int NTILES = NT64*(NT64+1)/2;

    const int sys = blockIdx.y;
    const int tid = threadIdx.x;
    const float* Pp = g_P + (size_t)sys*NB*PROW;

    if ((int)blockIdx.x == NTILES) {
        __shared__ float ys[NB];
        if (tid < NB) ys[tid] = g_RHS[sys*KDIM + K0 + tid];
        __syncthreads();
        for (int r = tid; r < T; r += 256) {
            float s = g_RHS[sys*KDIM + KEND + r];
            #pragma unroll
            for (int m = 0; m < NB; ++m) s = fmaf(-Pp[m*PROW + r], ys[m], s);
            g_RHS[sys*KDIM + KEND + r] = s;
        }
        return;
    }

    int rem = blockIdx.x, ri = 0;
    while (rem > ri) { rem -= ri + 1; ++ri; }
    const int cj = rem;

    __shared__ float As[NB][68];
    __shared__ float Bs[NB][68];
    for (int idx = tid; idx < NB*64; idx += 256) {
        int k = idx >> 6, rr = idx & 63;
        int ra = 64*ri + rr;
        int rb = 64*cj + rr;
        As[k][rr] = (ra < T) ? Pp[k*PROW + ra] : 0.f;
        Bs[k][rr] = (rb < T) ? Pp[k*PROW + rb] : 0.f;
    }
    __syncthreads();

    const int tx = tid & 15;
    const int ty = tid >> 4;

    float acc[4][4];
    #pragma unroll
    for (int i2 = 0; i2 < 4; ++i2)
        #pragma unroll
        for (int j2 = 0; j2 < 4; ++j2) acc[i2][j2] = 0.f;

    #pragma unroll
    for (int k = 0; k < NB; ++k) {
        float4 av = *reinterpret_cast<const float4*>(&As[k][4*ty]);
        float4 bv = *reinterpret_cast<const float4*>(&Bs[k][4*tx]);
        float am[4] = {av.x,av.y,av.z,av.w};
        float bn[4] = {bv.x,bv.y,bv.z,bv.w};
        #pragma unroll
        for (int i2 = 0; i2 < 4; ++i2)
            #pragma unroll
            for (int j2 = 0; j2 < 4; ++j2)
                acc[i2][j2] = fmaf(am[i2], bn[j2], acc[i2][j2]);
    }

    float* M = g_M + (size_t)sys*KDIM*MROW;
    const int b = sys / KDIM;
    const float* Sb = g_S + (size_t)b*KDIM*KDIM;

    #pragma unroll
    for (int i2 = 0; i2 < 4; ++i2) {
        const int rr = 64*ri + 4*ty + i2;
        if (rr >= T) continue;
        const int i = KEND + rr;
        const int ccb = 64*cj + 4*tx;
        if (ccb + 3 < rr) {
            float4 v;
            if (P == 0) v = *reinterpret_cast<const float4*>(&Sb[(size_t)i*KDIM + KEND + ccb]);
            else        v = *reinterpret_cast<const float4*>(&M[(size_t)i*MROW + KEND + ccb]);
            v.x -= acc[i2][0]; v.y -= acc[i2][1];
            v.z -= acc[i2][2]; v.w -= acc[i2][3];
            *reinterpret_cast<float4*>(&M[(size_t)i*MROW + KEND + ccb]) = v;
        } else if (ccb <= rr) {
            #pragma unroll
            for (int q = 0; q < 4; ++q) {
                const int c = ccb + q;
                if (c > rr) break;
                float v;
                if (P == 0) {
                    v = Sb[(size_t)i*KDIM + KEND + c];
                    if (c == rr) v += g_DSH[sys*KDIM + i];
                } else {
                    v = M[(size_t)i*MROW + KEND + c];
                }
                M[(size_t)i*MROW + KEND + c] = v - acc[i2][q];
            }
        }
    }
}

// ---------------------------------------------------------------------------
// k_back<BLK>: one backward-substitution block step; writes final x to out.
// grid (NSYS), 192 thr.
// ---------------------------------------------------------------------------
template<int BLK>
__global__ __launch_bounds__(192) void k_back(float* __restrict__ out)
{
    constexpr int BK0 = BLK*NB;
    const unsigned FMASK = 0x000FFFFFu;
    __shared__ float xs[NB];

    const int sys = blockIdx.x;
    const int tid = threadIdx.x;
    const int lane = tid & 31;
    const int wid  = tid >> 5;
    const float* M = g_M + (size_t)sys*KDIM*MROW;

    if (wid == 0 && lane < NB) {
        float a[NB];
        #pragma unroll
        for (int m = 0; m < NB; ++m)
            a[m] = (m >= lane) ? M[(size_t)(BK0 + m)*MROW + BK0 + lane] : 0.f;
        float dv = g_DINV[sys*KDIM + BK0 + lane];
        float r  = g_RHS[sys*KDIM + BK0 + lane];
        #pragma unroll
        for (int m = NB - 1; m >= 0; --m) {
            float xm = __shfl_sync(FMASK, r, m) * __shfl_sync(FMASK, dv, m);
            if (lane == m) r = xm;
            if (lane <  m) r = fmaf(-a[m], xm, r);
        }
        xs[lane] = r;
        out[(size_t)sys*KDIM + BK0 + lane] = r;
    }
    __syncthreads();

    for (int i = tid; i < BK0; i += 192) {
        float s = g_RHS[sys*KDIM + i];
        #pragma unroll
        for (int m = 0; m < NB; ++m)
            s = fmaf(-M[(size_t)(BK0 + m)*MROW + i], xs[m], s);
        g_RHS[sys*KDIM + i] = s;
    }
}

// ---------------------------------------------------------------------------
extern "C" void kernel_launch(void* const* d_in, const int* in_sizes, int n_in,
                              void* d_out, int out_size)
{
    const float* feat_x  = (const float*)d_in[0];
    const float* feat_y  = (const float*)d_in[1];
    const float* evals_x = (const float*)d_in[2];
    const float* evals_y = (const float*)d_in[3];
    const float* evtx    = (const float*)d_in[4];
    const float* evty    = (const float*)d_in[5];
    const float* graw    = (const float*)d_in[6];
    const float* lraw    = (const float*)d_in[7];
    float* out = (float*)d_out;

    k_gemm_feat<<<dim3(4, 4, 48), 256>>>(feat_x, feat_y, evtx, evty);
    k_gemm_gram<<<dim3(4, 4, 16), 256>>>();
    k_prep<<<dim3(KDIM, BATCH), 256>>>(evals_x, evals_y, graw, lraw);

    k_panel<0><<<NSYS, 192>>>();  k_trail<0><<<dim3(7, NSYS), 256>>>();
    k_panel<1><<<NSYS, 192>>>();  k_trail<1><<<dim3(7, NSYS), 256>>>();
    k_panel<2><<<NSYS, 192>>>();  k_trail<2><<<dim3(7, NSYS), 256>>>();
    k_panel<3><<<NSYS, 192>>>();  k_trail<3><<<dim3(4, NSYS), 256>>>();
    k_panel<4><<<NSYS, 192>>>();  k_trail<4><<<dim3(4, NSYS), 256>>>();
    k_panel<5><<<NSYS, 192>>>();  k_trail<5><<<dim3(4, NSYS), 256>>>();
    k_panel<6><<<NSYS, 192>>>();  k_trail<6><<<dim3(2, NSYS), 256>>>();
    k_panel<7><<<NSYS, 192>>>();  k_trail<7><<<dim3(2, NSYS), 256>>>();
    k_panel<8><<<NSYS, 192>>>();  k_trail<8><<<dim3(2, NSYS), 256>>>();
    k_panel<9><<<NSYS, 192>>>();

    k_back<9><<<NSYS, 192>>>(out);
    k_back<8><<<NSYS, 192>>>(out);
    k_back<7><<<NSYS, 192>>>(out);
    k_back<6><<<NSYS, 192>>>(out);
    k_back<5><<<NSYS, 192>>>(out);
    k_back<4><<<NSYS, 192>>>(out);
    k_back<3><<<NSYS, 192>>>(out);
    k_back<2><<<NSYS, 192>>>(out);
    k_back<1><<<NSYS, 192>>>(out);
    k_back<0><<<NSYS, 192>>>(out);
}